// round 6
// baseline (speedup 1.0000x reference)
#include <cuda_runtime.h>
#include <cuda_bf16.h>
#include <mma.h>
#include <cstdint>

using namespace nvcuda;

#define T_   4
#define B_   32
#define C_   384
#define N_   256
#define H_   8
#define D_   48
#define TB_  (T_ * B_)
#define BCN_ (B_ * C_ * N_)      // 3,145,728
#define TOT_ (T_ * BCN_)         // 12,582,912
#define M3_  (3 * C_)            // 1152
#define BON_ (B_ * M3_ * N_)     // 9,437,184

// ---------------- scratch (device globals) ----------------------------------------
__device__ __nv_bfloat16 g_s1[TOT_];           // spikes after lif1   [tb][c][n]
__device__ __nv_bfloat16 g_sq[TOT_];           // q spikes            [tb][c][n]
__device__ __nv_bfloat16 g_sk[TOT_];
__device__ __nv_bfloat16 g_sv[TOT_];
__device__ __nv_bfloat16 g_s2[TOT_];           // attn-lif spikes
__device__ float         g_y3[3 * TOT_];       // fused qkv GEMM out  [tb][1152][n]
__device__ __nv_bfloat16 g_whi[4 * C_ * C_];   // hi bf16 of inv-scaled weights
__device__ __nv_bfloat16 g_wlo[4 * C_ * C_];   // lo residual
__device__ float         g_bns[4 * C_];        // folded BN scale
__device__ float         g_bnb[4 * C_];        // folded BN shift

// ---------------- prep ------------------------------------------------------------
__global__ void bnfold_kernel(const float* qg, const float* qb, const float* qm, const float* qv,
                              const float* kg, const float* kb, const float* km, const float* kv,
                              const float* vg, const float* vb, const float* vm, const float* vv,
                              const float* pg, const float* pb, const float* pm, const float* pv,
                              const float* pbias)
{
    int i = blockIdx.x * 256 + threadIdx.x;
    if (i >= 4 * C_) return;
    int s = i / C_, c = i - s * C_;
    const float *G, *Bt, *M, *V;
    if      (s == 0) { G = qg; Bt = qb; M = qm; V = qv; }
    else if (s == 1) { G = kg; Bt = kb; M = km; V = kv; }
    else if (s == 2) { G = vg; Bt = vb; M = vm; V = vv; }
    else             { G = pg; Bt = pb; M = pm; V = pv; }
    float inv = G[c] / sqrtf(V[c] + 1e-5f);
    float add = Bt[c] - M[c] * inv;
    if (s == 3) add += pbias[c] * inv;
    g_bns[i] = inv;
    g_bnb[i] = add;
}

// weight split with BN scale folded in: W' = inv[o] * W; W' = hi + lo
__global__ void wconv_kernel(const float* __restrict__ w0, const float* __restrict__ w1,
                             const float* __restrict__ w2, const float* __restrict__ w3)
{
    int i = blockIdx.x * 256 + threadIdx.x;
    if (i >= 4 * C_ * C_) return;
    int s = i / (C_ * C_);
    int j = i - s * (C_ * C_);
    int o = j / C_;
    const float* w = (s == 0) ? w0 : (s == 1) ? w1 : (s == 2) ? w2 : w3;
    float val = w[j] * g_bns[s * C_ + o];
    __nv_bfloat16 hi = __float2bfloat16(val);
    g_whi[i] = hi;
    g_wlo[i] = __float2bfloat16(val - __bfloat162float(hi));
}

// ---------------- LIF -------------------------------------------------------------
__global__ void lif_kernel(const float* __restrict__ xin, __nv_bfloat16* __restrict__ sout)
{
    int i = blockIdx.x * 256 + threadIdx.x;
    if (i >= BCN_) return;
    float v = 0.f;
#pragma unroll
    for (int t = 0; t < T_; t++) {
        float xv = xin[(size_t)t * BCN_ + i];
        float h = v + (xv - v) * 0.5f;
        bool sp = (h >= 1.0f);
        sout[(size_t)t * BCN_ + i] = __float2bfloat16(sp ? 1.f : 0.f);
        v = sp ? 0.f : h;
    }
}

__global__ void lif3_kernel(const float* __restrict__ y,
                            __nv_bfloat16* __restrict__ oq,
                            __nv_bfloat16* __restrict__ ok,
                            __nv_bfloat16* __restrict__ ov)
{
    int i = blockIdx.x * 256 + threadIdx.x;
    if (i >= BON_) return;
    int n = i & (N_ - 1);
    int o = (i >> 8) % M3_;
    int b = i / (M3_ * N_);
    int s = o / C_;
    int oc = o - s * C_;
    __nv_bfloat16* outp = (s == 0) ? oq : (s == 1) ? ok : ov;
    size_t ibase = ((size_t)b * M3_ + o) * N_ + n;
    size_t obase = ((size_t)b * C_ + oc) * N_ + n;
    float v = 0.f;
#pragma unroll
    for (int t = 0; t < T_; t++) {
        float xv = y[(size_t)t * BON_ + ibase];
        float h = v + (xv - v) * 0.5f;
        bool sp = (h >= 1.0f);
        outp[(size_t)t * BCN_ + obase] = __float2bfloat16(sp ? 1.f : 0.f);
        v = sp ? 0.f : h;
    }
}

// ---------------- cp.async helpers ------------------------------------------------
__device__ __forceinline__ void cpa16(void* s, const void* g)
{
    unsigned int sa = (unsigned int)__cvta_generic_to_shared(s);
    asm volatile("cp.async.cg.shared.global [%0], [%1], 16;\n" :: "r"(sa), "l"(g));
}
__device__ __forceinline__ void cpa_commit() { asm volatile("cp.async.commit_group;\n"); }
template <int N>
__device__ __forceinline__ void cpa_wait() { asm volatile("cp.async.wait_group %0;\n" :: "n"(N)); }

// ---------------- batched GEMM + folded BN (hi/lo share B tile) -------------------
// out[tb][o][n] = (W'hi + W'lo)[o][:] . S[tb][:][n] + bnb[o]
#define GBM 128
#define GBN 128
#define GBK 64
#define LDA 72
#define LDB 136
#define NT_ 6
#define ASTG (2 * GBM * LDA)
#define GSM ((2 * ASTG + 2 * GBK * LDB) * 2)   // 108544 B

__global__ __launch_bounds__(256, 2)
void gemm_bn_kernel(const __nv_bfloat16* __restrict__ Ahi,
                    const __nv_bfloat16* __restrict__ Alo,
                    const __nv_bfloat16* __restrict__ Bmat,
                    int ldo, int bnoff, float* __restrict__ out)
{
    extern __shared__ char smem[];
    __nv_bfloat16* As = (__nv_bfloat16*)smem;
    __nv_bfloat16* Bs = (__nv_bfloat16*)(smem + 2 * ASTG * 2);
    float*         Cs = (float*)smem;

    int o0 = blockIdx.x * GBM;
    int n0 = blockIdx.y * GBN;
    int tb = blockIdx.z;
    const __nv_bfloat16* Bp = Bmat + (size_t)tb * C_ * N_;
    int tid = threadIdx.x;
    int wid = tid >> 5;
    int wm = wid & 1;
    int wn = wid >> 1;

    wmma::fragment<wmma::accumulator, 16, 16, 16, float> acc[4][2];
#pragma unroll
    for (int i = 0; i < 4; i++)
#pragma unroll
        for (int j = 0; j < 2; j++) wmma::fill_fragment(acc[i][j], 0.f);

    auto issue = [&](int kt, int st) {
        int ka = kt * GBK;
        __nv_bfloat16* Ad = As + st * ASTG;
        __nv_bfloat16* Al = Ad + GBM * LDA;
        __nv_bfloat16* Bd = Bs + st * GBK * LDB;
#pragma unroll
        for (int u = 0; u < 4; u++) {
            int idx = tid + u * 256;
            int r = idx >> 3, col = (idx & 7) << 3;
            size_t go = (size_t)(o0 + r) * C_ + ka + col;
            cpa16(Ad + r * LDA + col, Ahi + go);
            cpa16(Al + r * LDA + col, Alo + go);
        }
#pragma unroll
        for (int u = 0; u < 4; u++) {
            int idx = tid + u * 256;
            int r = idx >> 4, col = (idx & 15) << 3;
            cpa16(Bd + r * LDB + col, Bp + (size_t)(ka + r) * N_ + n0 + col);
        }
        cpa_commit();
    };

    issue(0, 0);
    for (int kt = 0; kt < NT_; kt++) {
        if (kt + 1 < NT_) issue(kt + 1, (kt + 1) & 1);
        if (kt + 1 < NT_) cpa_wait<1>(); else cpa_wait<0>();
        __syncthreads();
        const __nv_bfloat16* Ah = As + (kt & 1) * ASTG;
        const __nv_bfloat16* Al = Ah + GBM * LDA;
        const __nv_bfloat16* Bb = Bs + (kt & 1) * GBK * LDB;
#pragma unroll
        for (int ks = 0; ks < 4; ks++) {
            wmma::fragment<wmma::matrix_b, 16, 16, 16, __nv_bfloat16, wmma::row_major> bfr[2];
#pragma unroll
            for (int j = 0; j < 2; j++)
                wmma::load_matrix_sync(bfr[j], Bb + (ks * 16) * LDB + wn * 32 + j * 16, LDB);
            wmma::fragment<wmma::matrix_a, 16, 16, 16, __nv_bfloat16, wmma::row_major> af[4];
#pragma unroll
            for (int i = 0; i < 4; i++)
                wmma::load_matrix_sync(af[i], Ah + (wm * 64 + i * 16) * LDA + ks * 16, LDA);
#pragma unroll
            for (int i = 0; i < 4; i++)
#pragma unroll
                for (int j = 0; j < 2; j++)
                    wmma::mma_sync(acc[i][j], af[i], bfr[j], acc[i][j]);
#pragma unroll
            for (int i = 0; i < 4; i++)
                wmma::load_matrix_sync(af[i], Al + (wm * 64 + i * 16) * LDA + ks * 16, LDA);
#pragma unroll
            for (int i = 0; i < 4; i++)
#pragma unroll
                for (int j = 0; j < 2; j++)
                    wmma::mma_sync(acc[i][j], af[i], bfr[j], acc[i][j]);
        }
        __syncthreads();
    }

#pragma unroll
    for (int i = 0; i < 4; i++)
#pragma unroll
        for (int j = 0; j < 2; j++)
            wmma::store_matrix_sync(Cs + (wm * 64 + i * 16) * GBN + wn * 32 + j * 16,
                                    acc[i][j], GBN, wmma::mem_row_major);
    __syncthreads();

#pragma unroll
    for (int u = 0; u < 16; u++) {
        int e = tid + u * 256;
        int r = e >> 5;
        int c4 = (e & 31) << 2;
        int o = o0 + r;
        float add = g_bnb[bnoff + o];
        float4 val = *(float4*)(Cs + r * GBN + c4);
        val.x += add; val.y += add; val.z += add; val.w += add;
        *(float4*)(out + ((size_t)tb * ldo + o) * N_ + n0 + c4) = val;
    }
}

// ---------------- tensor-core attention + fused attn-LIF --------------------------
// One block per (b,h); loops t=0..3 keeping LIF membrane in registers.
// Emits bf16 spikes directly to g_s2 [t*B+b][c][n].
#define LDQ 264     // 256 + 8
#define LDS 72      // 64 + 8
#define ASM_ (3 * 64 * LDQ * 2 + 256 * LDS * 2 + 8 * 256 * 4 + 64 * LDS * 4)  // 164864

__global__ __launch_bounds__(256)
void attn_kernel(const __nv_bfloat16* __restrict__ q, const __nv_bfloat16* __restrict__ k,
                 const __nv_bfloat16* __restrict__ v, __nv_bfloat16* __restrict__ s2out)
{
    extern __shared__ char smraw[];
    __nv_bfloat16* Qs = (__nv_bfloat16*)smraw;             // [64][LDQ]
    __nv_bfloat16* Ks = Qs + 64 * LDQ;
    __nv_bfloat16* Vs = Ks + 64 * LDQ;
    __nv_bfloat16* STb = Vs + 64 * LDQ;                    // S^T [256][LDS]
    float* scratch = (float*)(STb + 256 * LDS);
    float* Osm = scratch + 8 * 256;                        // [64][LDS]

    int bh = blockIdx.x;
    int b = bh >> 3, h = bh & 7;
    int tid = threadIdx.x;
    int wid = tid >> 5;
    int lane = tid & 31;

    // LIF membrane: per thread, 4 nt-tiles x 3 chunks x 4 elems
    float4 vm[4][3];
#pragma unroll
    for (int a = 0; a < 4; a++)
#pragma unroll
        for (int u = 0; u < 3; u++) vm[a][u] = make_float4(0.f, 0.f, 0.f, 0.f);

#pragma unroll 1
    for (int t = 0; t < T_; t++) {
        size_t base = (((size_t)(t * B_ + b)) * C_ + h * D_) * N_;

        const __nv_bfloat16* srcs[3] = { q + base, k + base, v + base };
        __nv_bfloat16* dsts[3] = { Qs, Ks, Vs };
#pragma unroll
        for (int mtx = 0; mtx < 3; mtx++) {
#pragma unroll
            for (int u = 0; u < 6; u++) {
                int idx = tid + u * 256;
                int r = idx >> 5, col = (idx & 31) << 3;
                *(uint4*)(dsts[mtx] + r * LDQ + col) =
                    *(const uint4*)(srcs[mtx] + (size_t)r * N_ + col);
            }
#pragma unroll
            for (int u = 0; u < 2; u++) {
                int idx = tid + u * 256;
                int r = 48 + (idx >> 5), col = (idx & 31) << 3;
                *(uint4*)(dsts[mtx] + r * LDQ + col) = make_uint4(0, 0, 0, 0);
            }
        }
        __syncthreads();

        int wr = wid & 1;
        int wc = wid >> 1;

#pragma unroll 1
        for (int nt = 0; nt < 4; nt++) {
            int n0 = nt * 64;

            // stage 1: S[n0..n0+63][0..255] = Q^T K
            wmma::fragment<wmma::accumulator, 16, 16, 16, float> sacc[2][4];
#pragma unroll
            for (int i = 0; i < 2; i++)
#pragma unroll
                for (int j = 0; j < 4; j++) wmma::fill_fragment(sacc[i][j], 0.f);
#pragma unroll
            for (int dk = 0; dk < 64; dk += 16) {
                wmma::fragment<wmma::matrix_a, 16, 16, 16, __nv_bfloat16, wmma::col_major> af[2];
                wmma::fragment<wmma::matrix_b, 16, 16, 16, __nv_bfloat16, wmma::row_major> bfr[4];
#pragma unroll
                for (int i = 0; i < 2; i++)
                    wmma::load_matrix_sync(af[i], Qs + dk * LDQ + n0 + wr * 32 + i * 16, LDQ);
#pragma unroll
                for (int j = 0; j < 4; j++)
                    wmma::load_matrix_sync(bfr[j], Ks + dk * LDQ + wc * 64 + j * 16, LDQ);
#pragma unroll
                for (int i = 0; i < 2; i++)
#pragma unroll
                    for (int j = 0; j < 4; j++)
                        wmma::mma_sync(sacc[i][j], af[i], bfr[j], sacc[i][j]);
            }
            float* scr = scratch + wid * 256;
#pragma unroll
            for (int i = 0; i < 2; i++)
#pragma unroll
                for (int j = 0; j < 4; j++) {
                    wmma::store_matrix_sync(scr, sacc[i][j], 16, wmma::mem_col_major);
                    __syncwarp();
#pragma unroll
                    for (int e = 0; e < 8; e++) {
                        int idx = lane + e * 32;
                        int ni = idx & 15, mj = idx >> 4;
                        STb[(wc * 64 + j * 16 + mj) * LDS + wr * 32 + i * 16 + ni] =
                            __float2bfloat16(scr[idx]);
                    }
                    __syncwarp();
                }
            __syncthreads();

            // stage 2: O[0..63][n0..n0+63] = V S^T (scaled by 0.125)
            int dr = wid & 1;
            int nc = wid >> 1;
            wmma::fragment<wmma::accumulator, 16, 16, 16, float> oacc[2];
#pragma unroll
            for (int i = 0; i < 2; i++) wmma::fill_fragment(oacc[i], 0.f);
#pragma unroll
            for (int m = 0; m < 256; m += 16) {
                wmma::fragment<wmma::matrix_a, 16, 16, 16, __nv_bfloat16, wmma::row_major> av[2];
                wmma::fragment<wmma::matrix_b, 16, 16, 16, __nv_bfloat16, wmma::row_major> bs;
#pragma unroll
                for (int i = 0; i < 2; i++)
                    wmma::load_matrix_sync(av[i], Vs + (dr * 32 + i * 16) * LDQ + m, LDQ);
                wmma::load_matrix_sync(bs, STb + m * LDS + nc * 16, LDS);
#pragma unroll
                for (int i = 0; i < 2; i++)
                    wmma::mma_sync(oacc[i], av[i], bs, oacc[i]);
            }
#pragma unroll
            for (int i = 0; i < 2; i++) {
#pragma unroll
                for (int e = 0; e < oacc[i].num_elements; e++) oacc[i].x[e] *= 0.125f;
                wmma::store_matrix_sync(Osm + (dr * 32 + i * 16) * LDS + nc * 16,
                                        oacc[i], LDS, wmma::mem_row_major);
            }
            __syncthreads();

            // fused LIF epilogue: d<48 rows, write bf16 spikes
#pragma unroll
            for (int u = 0; u < 3; u++) {
                int e = tid + u * 256;
                int d = e >> 4, c4 = (e & 15) << 2;
                float4 xv = *(float4*)(Osm + d * LDS + c4);
                float4 mv = vm[nt][u];
                __nv_bfloat162 o01, o23;
                float hh, s0, s1v, s2v, s3v;
                hh = mv.x + (xv.x - mv.x) * 0.5f; s0 = (hh >= 1.f) ? 1.f : 0.f; mv.x = (hh >= 1.f) ? 0.f : hh;
                hh = mv.y + (xv.y - mv.y) * 0.5f; s1v = (hh >= 1.f) ? 1.f : 0.f; mv.y = (hh >= 1.f) ? 0.f : hh;
                hh = mv.z + (xv.z - mv.z) * 0.5f; s2v = (hh >= 1.f) ? 1.f : 0.f; mv.z = (hh >= 1.f) ? 0.f : hh;
                hh = mv.w + (xv.w - mv.w) * 0.5f; s3v = (hh >= 1.f) ? 1.f : 0.f; mv.w = (hh >= 1.f) ? 0.f : hh;
                vm[nt][u] = mv;
                o01 = __floats2bfloat162_rn(s0, s1v);
                o23 = __floats2bfloat162_rn(s2v, s3v);
                size_t ob = (((size_t)(t * B_ + b)) * C_ + h * D_ + d) * N_ + n0 + c4;
                *(__nv_bfloat162*)(s2out + ob) = o01;
                *(__nv_bfloat162*)(s2out + ob + 2) = o23;
            }
            __syncthreads();
        }
    }
}

// ---------------- launch ----------------------------------------------------------
extern "C" void kernel_launch(void* const* d_in, const int* in_sizes, int n_in,
                              void* d_out, int out_size)
{
    const float* x   = (const float*)d_in[0];
    const float* qw  = (const float*)d_in[2];
    const float* qg  = (const float*)d_in[3];
    const float* qb  = (const float*)d_in[4];
    const float* qm  = (const float*)d_in[5];
    const float* qv  = (const float*)d_in[6];
    const float* kw  = (const float*)d_in[7];
    const float* kg  = (const float*)d_in[8];
    const float* kb  = (const float*)d_in[9];
    const float* km  = (const float*)d_in[10];
    const float* kv  = (const float*)d_in[11];
    const float* vw  = (const float*)d_in[12];
    const float* vg  = (const float*)d_in[13];
    const float* vb  = (const float*)d_in[14];
    const float* vm  = (const float*)d_in[15];
    const float* vv  = (const float*)d_in[16];
    const float* pw  = (const float*)d_in[17];
    const float* pbias = (const float*)d_in[18];
    const float* pg  = (const float*)d_in[19];
    const float* pb  = (const float*)d_in[20];
    const float* pm  = (const float*)d_in[21];
    const float* pv  = (const float*)d_in[22];

    void *ps1, *psq, *psk, *psv, *ps2, *py3, *phi, *plo;
    cudaGetSymbolAddress(&ps1, g_s1);
    cudaGetSymbolAddress(&psq, g_sq);
    cudaGetSymbolAddress(&psk, g_sk);
    cudaGetSymbolAddress(&psv, g_sv);
    cudaGetSymbolAddress(&ps2, g_s2);
    cudaGetSymbolAddress(&py3, g_y3);
    cudaGetSymbolAddress(&phi, g_whi);
    cudaGetSymbolAddress(&plo, g_wlo);
    __nv_bfloat16* s1  = (__nv_bfloat16*)ps1;
    __nv_bfloat16* sq  = (__nv_bfloat16*)psq;
    __nv_bfloat16* sk  = (__nv_bfloat16*)psk;
    __nv_bfloat16* sv  = (__nv_bfloat16*)psv;
    __nv_bfloat16* s2  = (__nv_bfloat16*)ps2;
    float*         y3  = (float*)py3;
    __nv_bfloat16* whi = (__nv_bfloat16*)phi;
    __nv_bfloat16* wlo = (__nv_bfloat16*)plo;

    cudaFuncSetAttribute(gemm_bn_kernel, cudaFuncAttributeMaxDynamicSharedMemorySize, GSM);
    cudaFuncSetAttribute(attn_kernel, cudaFuncAttributeMaxDynamicSharedMemorySize, ASM_);

    // prep: BN fold first (wconv consumes g_bns)
    bnfold_kernel<<<6, 256>>>(qg, qb, qm, qv, kg, kb, km, kv,
                              vg, vb, vm, vv, pg, pb, pm, pv, pbias);
    wconv_kernel<<<(4 * C_ * C_ + 255) / 256, 256>>>(qw, kw, vw, pw);
    // proj_lif on input
    lif_kernel<<<BCN_ / 256, 256>>>(x, s1);
    // fused q,k,v GEMM + BN
    gemm_bn_kernel<<<dim3(M3_ / GBM, N_ / GBN, TB_), 256, GSM>>>(
        whi, wlo, s1, M3_, 0, y3);
    // LIF over the three branches
    lif3_kernel<<<BON_ / 256, 256>>>(y3, sq, sk, sv);
    // attention + fused attn-LIF -> bf16 spikes
    attn_kernel<<<B_ * H_, 256, ASM_>>>(sq, sk, sv, s2);
    // proj GEMM + bias + BN -> final output
    gemm_bn_kernel<<<dim3(C_ / GBM, N_ / GBN, TB_), 256, GSM>>>(
        whi + 3 * C_ * C_, wlo + 3 * C_ * C_, s2, C_, 3 * C_, (float*)d_out);
}

// round 8
// speedup vs baseline: 1.0716x; 1.0716x over previous
#include <cuda_runtime.h>
#include <cuda_bf16.h>
#include <mma.h>
#include <cstdint>

using namespace nvcuda;

#define T_   4
#define B_   32
#define C_   384
#define N_   256
#define H_   8
#define D_   48
#define TB_  (T_ * B_)
#define TBH_ (TB_ * H_)
#define BCN_ (B_ * C_ * N_)      // 3,145,728
#define TOT_ (T_ * BCN_)         // 12,582,912
#define M3_  (3 * C_)            // 1152
#define BON_ (B_ * M3_ * N_)     // 9,437,184

// ---------------- scratch (device globals) ----------------------------------------
__device__ __nv_bfloat16 g_s1[TOT_];           // spikes after lif1   [tb][c][n]
__device__ __nv_bfloat16 g_sq[TOT_];           // q spikes            [tb][c][n]
__device__ __nv_bfloat16 g_sk[TOT_];
__device__ __nv_bfloat16 g_sv[TOT_];
__device__ __nv_bfloat16 g_s2[TOT_];           // attn-lif spikes
__device__ float         g_y3[3 * TOT_];       // fused qkv GEMM out  [tb][1152][n]
__device__ float         g_ya[TOT_];           // attention out fp32  [tb][c][n]
__device__ __nv_bfloat16 g_whi[4 * C_ * C_];   // hi bf16 of BN-scaled weights
__device__ __nv_bfloat16 g_wlo[4 * C_ * C_];   // lo residual
__device__ float         g_bns[4 * C_];        // folded BN scale
__device__ float         g_bnb[4 * C_];        // folded BN shift

// ---------------- prep ------------------------------------------------------------
__global__ void bnfold_kernel(const float* qg, const float* qb, const float* qm, const float* qv,
                              const float* kg, const float* kb, const float* km, const float* kv,
                              const float* vg, const float* vb, const float* vm, const float* vv,
                              const float* pg, const float* pb, const float* pm, const float* pv,
                              const float* pbias)
{
    int i = blockIdx.x * 256 + threadIdx.x;
    if (i >= 4 * C_) return;
    int s = i / C_, c = i - s * C_;
    const float *G, *Bt, *M, *V;
    if      (s == 0) { G = qg; Bt = qb; M = qm; V = qv; }
    else if (s == 1) { G = kg; Bt = kb; M = km; V = kv; }
    else if (s == 2) { G = vg; Bt = vb; M = vm; V = vv; }
    else             { G = pg; Bt = pb; M = pm; V = pv; }
    float inv = G[c] / sqrtf(V[c] + 1e-5f);
    float add = Bt[c] - M[c] * inv;
    if (s == 3) add += pbias[c] * inv;
    g_bns[i] = inv;
    g_bnb[i] = add;
}

// weight split with BN scale folded: W' = inv[o] * W; W' = hi + lo
__global__ void wconv_kernel(const float* __restrict__ w0, const float* __restrict__ w1,
                             const float* __restrict__ w2, const float* __restrict__ w3)
{
    int i = blockIdx.x * 256 + threadIdx.x;
    if (i >= 4 * C_ * C_) return;
    int s = i / (C_ * C_);
    int j = i - s * (C_ * C_);
    int o = j / C_;
    const float* w = (s == 0) ? w0 : (s == 1) ? w1 : (s == 2) ? w2 : w3;
    float val = w[j] * g_bns[s * C_ + o];
    __nv_bfloat16 hi = __float2bfloat16(val);
    g_whi[i] = hi;
    g_wlo[i] = __float2bfloat16(val - __bfloat162float(hi));
}

// ---------------- LIF -------------------------------------------------------------
__global__ void lif_kernel(const float* __restrict__ xin, __nv_bfloat16* __restrict__ sout)
{
    int i = blockIdx.x * 256 + threadIdx.x;
    if (i >= BCN_) return;
    float v = 0.f;
#pragma unroll
    for (int t = 0; t < T_; t++) {
        float xv = xin[(size_t)t * BCN_ + i];
        float h = v + (xv - v) * 0.5f;
        bool sp = (h >= 1.0f);
        sout[(size_t)t * BCN_ + i] = __float2bfloat16(sp ? 1.f : 0.f);
        v = sp ? 0.f : h;
    }
}

__global__ void lif3_kernel(const float* __restrict__ y,
                            __nv_bfloat16* __restrict__ oq,
                            __nv_bfloat16* __restrict__ ok,
                            __nv_bfloat16* __restrict__ ov)
{
    int i = blockIdx.x * 256 + threadIdx.x;
    if (i >= BON_) return;
    int n = i & (N_ - 1);
    int o = (i >> 8) % M3_;
    int b = i / (M3_ * N_);
    int s = o / C_;
    int oc = o - s * C_;
    __nv_bfloat16* outp = (s == 0) ? oq : (s == 1) ? ok : ov;
    size_t ibase = ((size_t)b * M3_ + o) * N_ + n;
    size_t obase = ((size_t)b * C_ + oc) * N_ + n;
    float v = 0.f;
#pragma unroll
    for (int t = 0; t < T_; t++) {
        float xv = y[(size_t)t * BON_ + ibase];
        float h = v + (xv - v) * 0.5f;
        bool sp = (h >= 1.0f);
        outp[(size_t)t * BCN_ + obase] = __float2bfloat16(sp ? 1.f : 0.f);
        v = sp ? 0.f : h;
    }
}

// ---------------- cp.async helpers ------------------------------------------------
__device__ __forceinline__ void cpa16(void* s, const void* g)
{
    unsigned int sa = (unsigned int)__cvta_generic_to_shared(s);
    asm volatile("cp.async.cg.shared.global [%0], [%1], 16;\n" :: "r"(sa), "l"(g));
}
__device__ __forceinline__ void cpa_commit() { asm volatile("cp.async.commit_group;\n"); }
template <int NN>
__device__ __forceinline__ void cpa_wait() { asm volatile("cp.async.wait_group %0;\n" :: "n"(NN)); }

// ---------------- batched GEMM + folded BN ----------------------------------------
// Block tile 128(o) x 256(n), 8 warps as 2(M) x 4(N), warp tile 64x64.
// 3-stage cp.async pipeline, single __syncthreads per k-iter.
// out[tb][o][n] = (W'hi + W'lo)[o][:] . S[tb][:][n] + bnb[o]
#define GBM 128
#define GBN 256
#define GBK 64
#define LDA 72                            // 64 + 8 pad
#define LDB 264                           // 256 + 8 pad
#define LDC 260                           // 256 + 4 pad (fp32)
#define NT_ 6                             // C_/GBK
#define A_ST (GBM * LDA)                  // one A matrix per stage (elems)
#define AST (2 * A_ST)                    // hi + lo
#define BST (GBK * LDB)
#define STG_ (AST + BST)                  // 35328 elems
#define GSM (3 * STG_ * 2)                // 211968 B

__global__ __launch_bounds__(256, 1)
void gemm_bn_kernel(const __nv_bfloat16* __restrict__ Ahi,
                    const __nv_bfloat16* __restrict__ Alo,
                    const __nv_bfloat16* __restrict__ Bmat,
                    int ldo, int bnoff, float* __restrict__ out)
{
    extern __shared__ char smem[];
    __nv_bfloat16* Sg = (__nv_bfloat16*)smem;
    float*         Cs = (float*)smem;     // epilogue reuse (128 x LDC)

    int o0 = blockIdx.x * GBM;
    int tb = blockIdx.z;
    const __nv_bfloat16* Bp = Bmat + (size_t)tb * C_ * N_;
    int tid = threadIdx.x;
    int wid = tid >> 5;
    int wm = wid & 1;          // 2 warps in M
    int wn = wid >> 1;         // 4 warps in N

    wmma::fragment<wmma::accumulator, 16, 16, 16, float> acc[4][4];
#pragma unroll
    for (int i = 0; i < 4; i++)
#pragma unroll
        for (int j = 0; j < 4; j++) wmma::fill_fragment(acc[i][j], 0.f);

    auto fill = [&](int kt, int st) {
        __nv_bfloat16* Ah = Sg + st * STG_;
        __nv_bfloat16* Al = Ah + A_ST;
        __nv_bfloat16* Bd = Ah + AST;
        int ka = kt * GBK;
#pragma unroll
        for (int u = 0; u < 4; u++) {            // A hi+lo: 128x64, 1024 chunks each
            int idx = tid + u * 256;
            int r = idx >> 3, c8 = (idx & 7) << 3;
            size_t go = (size_t)(o0 + r) * C_ + ka + c8;
            cpa16(Ah + r * LDA + c8, Ahi + go);
            cpa16(Al + r * LDA + c8, Alo + go);
        }
#pragma unroll
        for (int u = 0; u < 8; u++) {            // B: 64x256, 2048 chunks
            int idx = tid + u * 256;
            int r = idx >> 5, c8 = (idx & 31) << 3;
            cpa16(Bd + r * LDB + c8, Bp + (size_t)(ka + r) * N_ + c8);
        }
        cpa_commit();
    };

    fill(0, 0);
    fill(1, 1);
    for (int kt = 0; kt < NT_; kt++) {
        if (kt + 1 < NT_) cpa_wait<1>(); else cpa_wait<0>();
        __syncthreads();
        int st = kt % 3;
        const __nv_bfloat16* Ah = Sg + st * STG_;
        const __nv_bfloat16* Al = Ah + A_ST;
        const __nv_bfloat16* Bb = Ah + AST;
#pragma unroll
        for (int ks = 0; ks < 4; ks++) {
            wmma::fragment<wmma::matrix_b, 16, 16, 16, __nv_bfloat16, wmma::row_major> bfr[4];
#pragma unroll
            for (int j = 0; j < 4; j++)
                wmma::load_matrix_sync(bfr[j], Bb + (ks * 16) * LDB + wn * 64 + j * 16, LDB);
            wmma::fragment<wmma::matrix_a, 16, 16, 16, __nv_bfloat16, wmma::row_major> af[4];
#pragma unroll
            for (int i = 0; i < 4; i++)
                wmma::load_matrix_sync(af[i], Ah + (wm * 64 + i * 16) * LDA + ks * 16, LDA);
#pragma unroll
            for (int i = 0; i < 4; i++)
#pragma unroll
                for (int j = 0; j < 4; j++)
                    wmma::mma_sync(acc[i][j], af[i], bfr[j], acc[i][j]);
#pragma unroll
            for (int i = 0; i < 4; i++)
                wmma::load_matrix_sync(af[i], Al + (wm * 64 + i * 16) * LDA + ks * 16, LDA);
#pragma unroll
            for (int i = 0; i < 4; i++)
#pragma unroll
                for (int j = 0; j < 4; j++)
                    wmma::mma_sync(acc[i][j], af[i], bfr[j], acc[i][j]);
        }
        if (kt + 2 < NT_) fill(kt + 2, (kt + 2) % 3);
    }
    __syncthreads();    // all warps done reading smem before Cs overwrite

#pragma unroll
    for (int i = 0; i < 4; i++)
#pragma unroll
        for (int j = 0; j < 4; j++)
            wmma::store_matrix_sync(Cs + (wm * 64 + i * 16) * LDC + wn * 64 + j * 16,
                                    acc[i][j], LDC, wmma::mem_row_major);
    __syncthreads();

#pragma unroll
    for (int u = 0; u < 32; u++) {        // 8192 float4
        int e = tid + u * 256;
        int r = e >> 6;
        int c4 = (e & 63) << 2;
        int o = o0 + r;
        float add = g_bnb[bnoff + o];
        float4 val = *(float4*)(Cs + r * LDC + c4);
        val.x += add; val.y += add; val.z += add; val.w += add;
        *(float4*)(out + ((size_t)tb * ldo + o) * N_ + c4) = val;
    }
}

// ---------------- tensor-core attention -------------------------------------------
// Per (t,b,h): S = Qt K (exact int <=48 in bf16), O = V St * 0.125. Layout [d][n].
#define LDQ 264     // 256 + 8
#define LDS 72      // 64 + 8
#define ASM_ (3 * 64 * LDQ * 2 + 256 * LDS * 2 + 8 * 256 * 4 + 64 * LDS * 4)  // 164864

__global__ __launch_bounds__(256)
void attn_kernel(const __nv_bfloat16* __restrict__ q, const __nv_bfloat16* __restrict__ k,
                 const __nv_bfloat16* __restrict__ v, float* __restrict__ out)
{
    extern __shared__ char smraw[];
    __nv_bfloat16* Qs = (__nv_bfloat16*)smraw;             // [64][LDQ]
    __nv_bfloat16* Ks = Qs + 64 * LDQ;
    __nv_bfloat16* Vs = Ks + 64 * LDQ;
    __nv_bfloat16* STb = Vs + 64 * LDQ;                    // S^T [256][LDS]
    float* scratch = (float*)(STb + 256 * LDS);
    float* Osm = scratch + 8 * 256;                        // [64][LDS]

    int blk = blockIdx.x;
    int tb = blk >> 3, h = blk & 7;
    size_t base = ((size_t)tb * C_ + h * D_) * N_;
    int tid = threadIdx.x;
    int wid = tid >> 5;
    int lane = tid & 31;

    const __nv_bfloat16* srcs[3] = { q + base, k + base, v + base };
    __nv_bfloat16* dsts[3] = { Qs, Ks, Vs };
#pragma unroll
    for (int mtx = 0; mtx < 3; mtx++) {
#pragma unroll
        for (int u = 0; u < 6; u++) {
            int idx = tid + u * 256;
            int r = idx >> 5, col = (idx & 31) << 3;
            *(uint4*)(dsts[mtx] + r * LDQ + col) = *(const uint4*)(srcs[mtx] + (size_t)r * N_ + col);
        }
#pragma unroll
        for (int u = 0; u < 2; u++) {
            int idx = tid + u * 256;
            int r = 48 + (idx >> 5), col = (idx & 31) << 3;
            *(uint4*)(dsts[mtx] + r * LDQ + col) = make_uint4(0, 0, 0, 0);
        }
    }
    __syncthreads();

    int wr = wid & 1;
    int wc = wid >> 1;

#pragma unroll 1
    for (int nt = 0; nt < 4; nt++) {
        int n0 = nt * 64;

        wmma::fragment<wmma::accumulator, 16, 16, 16, float> sacc[2][4];
#pragma unroll
        for (int i = 0; i < 2; i++)
#pragma unroll
            for (int j = 0; j < 4; j++) wmma::fill_fragment(sacc[i][j], 0.f);
#pragma unroll
        for (int dk = 0; dk < 64; dk += 16) {
            wmma::fragment<wmma::matrix_a, 16, 16, 16, __nv_bfloat16, wmma::col_major> af[2];
            wmma::fragment<wmma::matrix_b, 16, 16, 16, __nv_bfloat16, wmma::row_major> bfr[4];
#pragma unroll
            for (int i = 0; i < 2; i++)
                wmma::load_matrix_sync(af[i], Qs + dk * LDQ + n0 + wr * 32 + i * 16, LDQ);
#pragma unroll
            for (int j = 0; j < 4; j++)
                wmma::load_matrix_sync(bfr[j], Ks + dk * LDQ + wc * 64 + j * 16, LDQ);
#pragma unroll
            for (int i = 0; i < 2; i++)
#pragma unroll
                for (int j = 0; j < 4; j++)
                    wmma::mma_sync(sacc[i][j], af[i], bfr[j], sacc[i][j]);
        }
        float* scr = scratch + wid * 256;
#pragma unroll
        for (int i = 0; i < 2; i++)
#pragma unroll
            for (int j = 0; j < 4; j++) {
                wmma::store_matrix_sync(scr, sacc[i][j], 16, wmma::mem_col_major);
                __syncwarp();
#pragma unroll
                for (int e = 0; e < 8; e++) {
                    int idx = lane + e * 32;
                    int ni = idx & 15, mj = idx >> 4;
                    STb[(wc * 64 + j * 16 + mj) * LDS + wr * 32 + i * 16 + ni] =
                        __float2bfloat16(scr[idx]);
                }
                __syncwarp();
            }
        __syncthreads();

        int dr = wid & 1;
        int nc = wid >> 1;
        wmma::fragment<wmma::accumulator, 16, 16, 16, float> oacc[2];
#pragma unroll
        for (int i = 0; i < 2; i++) wmma::fill_fragment(oacc[i], 0.f);
#pragma unroll
        for (int m = 0; m < 256; m += 16) {
            wmma::fragment<wmma::matrix_a, 16, 16, 16, __nv_bfloat16, wmma::row_major> av[2];
            wmma::fragment<wmma::matrix_b, 16, 16, 16, __nv_bfloat16, wmma::row_major> bs;
#pragma unroll
            for (int i = 0; i < 2; i++)
                wmma::load_matrix_sync(av[i], Vs + (dr * 32 + i * 16) * LDQ + m, LDQ);
            wmma::load_matrix_sync(bs, STb + m * LDS + nc * 16, LDS);
#pragma unroll
            for (int i = 0; i < 2; i++)
                wmma::mma_sync(oacc[i], av[i], bs, oacc[i]);
        }
#pragma unroll
        for (int i = 0; i < 2; i++) {
#pragma unroll
            for (int e = 0; e < oacc[i].num_elements; e++) oacc[i].x[e] *= 0.125f;
            wmma::store_matrix_sync(Osm + (dr * 32 + i * 16) * LDS + nc * 16,
                                    oacc[i], LDS, wmma::mem_row_major);
        }
        __syncthreads();

#pragma unroll
        for (int u = 0; u < 3; u++) {
            int e = tid + u * 256;
            int d = e >> 4, c4 = (e & 15) << 2;
            float4 val = *(float4*)(Osm + d * LDS + c4);
            *(float4*)(out + base + (size_t)d * N_ + n0 + c4) = val;
        }
        __syncthreads();
    }
}

// ---------------- launch ----------------------------------------------------------
extern "C" void kernel_launch(void* const* d_in, const int* in_sizes, int n_in,
                              void* d_out, int out_size)
{
    const float* x   = (const float*)d_in[0];
    const float* qw  = (const float*)d_in[2];
    const float* qg  = (const float*)d_in[3];
    const float* qb  = (const float*)d_in[4];
    const float* qm  = (const float*)d_in[5];
    const float* qv  = (const float*)d_in[6];
    const float* kw  = (const float*)d_in[7];
    const float* kg  = (const float*)d_in[8];
    const float* kb  = (const float*)d_in[9];
    const float* km  = (const float*)d_in[10];
    const float* kv  = (const float*)d_in[11];
    const float* vw  = (const float*)d_in[12];
    const float* vg  = (const float*)d_in[13];
    const float* vb  = (const float*)d_in[14];
    const float* vm  = (const float*)d_in[15];
    const float* vv  = (const float*)d_in[16];
    const float* pw  = (const float*)d_in[17];
    const float* pbias = (const float*)d_in[18];
    const float* pg  = (const float*)d_in[19];
    const float* pb  = (const float*)d_in[20];
    const float* pm  = (const float*)d_in[21];
    const float* pv  = (const float*)d_in[22];

    void *ps1, *psq, *psk, *psv, *ps2, *py3, *pya, *phi, *plo;
    cudaGetSymbolAddress(&ps1, g_s1);
    cudaGetSymbolAddress(&psq, g_sq);
    cudaGetSymbolAddress(&psk, g_sk);
    cudaGetSymbolAddress(&psv, g_sv);
    cudaGetSymbolAddress(&ps2, g_s2);
    cudaGetSymbolAddress(&py3, g_y3);
    cudaGetSymbolAddress(&pya, g_ya);
    cudaGetSymbolAddress(&phi, g_whi);
    cudaGetSymbolAddress(&plo, g_wlo);
    __nv_bfloat16* s1  = (__nv_bfloat16*)ps1;
    __nv_bfloat16* sq  = (__nv_bfloat16*)psq;
    __nv_bfloat16* sk  = (__nv_bfloat16*)psk;
    __nv_bfloat16* sv  = (__nv_bfloat16*)psv;
    __nv_bfloat16* s2  = (__nv_bfloat16*)ps2;
    float*         y3  = (float*)py3;
    float*         ya  = (float*)pya;
    __nv_bfloat16* whi = (__nv_bfloat16*)phi;
    __nv_bfloat16* wlo = (__nv_bfloat16*)plo;

    cudaFuncSetAttribute(gemm_bn_kernel, cudaFuncAttributeMaxDynamicSharedMemorySize, GSM);
    cudaFuncSetAttribute(attn_kernel, cudaFuncAttributeMaxDynamicSharedMemorySize, ASM_);

    // prep: BN fold first (wconv consumes g_bns)
    bnfold_kernel<<<6, 256>>>(qg, qb, qm, qv, kg, kb, km, kv,
                              vg, vb, vm, vv, pg, pb, pm, pv, pbias);
    wconv_kernel<<<(4 * C_ * C_ + 255) / 256, 256>>>(qw, kw, vw, pw);
    // proj_lif on input
    lif_kernel<<<BCN_ / 256, 256>>>(x, s1);
    // fused q,k,v GEMM + BN: 9 o-tiles x 128 tb
    gemm_bn_kernel<<<dim3(M3_ / GBM, 1, TB_), 256, GSM>>>(
        whi, wlo, s1, M3_, 0, y3);
    // LIF over the three branches
    lif3_kernel<<<BON_ / 256, 256>>>(y3, sq, sk, sv);
    // attention -> fp32
    attn_kernel<<<TBH_, 256, ASM_>>>(sq, sk, sv, ya);
    // attn_lif
    lif_kernel<<<BCN_ / 256, 256>>>(ya, s2);
    // proj GEMM + bias + BN -> final output
    gemm_bn_kernel<<<dim3(C_ / GBM, 1, TB_), 256, GSM>>>(
        whi + 3 * C_ * C_, wlo + 3 * C_ * C_, s2, C_, 3 * C_, (float*)d_out);
}